// round 6
// baseline (speedup 1.0000x reference)
#include <cuda_runtime.h>
#include <cuda_bf16.h>
#include <cstdint>

#define NN 50000
#define NE 600000
#define HIDD 128
#define AS 132                       // padded row stride (floats): conflict-free
#define SMEM_WORDS (3*128*AS + 4*128)
#define SMEM_BYTES (SMEM_WORDS*4)    // 204800 B
#define NB ((NN + 127) / 128)        // 391 tiles
#define NSB ((NN + 255) / 256)       // scan blocks (196)
#define PGRID 148                    // persistent grid

#define ST_AGG (1 << 30)
#define ST_INC (2 << 30)
#define VALMASK 0x3FFFFFFF

// ---------------- device scratch (static, no runtime alloc) ----------------
__device__ __align__(16) float g_x1[(size_t)NN * HIDD];
__device__ __align__(16) float g_x2[(size_t)NN * HIDD];
__device__ int   g_deg[NN];
__device__ int   g_rowptr[NN + 1];
__device__ int   g_cursor[NN];
__device__ int   g_esrc[NE];
__device__ int   g_lb[NSB];
__device__ float g_tap[4 * HIDD];

// ---------------- helpers ----------------
__device__ __forceinline__ unsigned f2t(float f) {
    unsigned u;
    asm("cvt.rna.tf32.f32 %0, %1;" : "=r"(u) : "f"(f));
    return u;
}

__device__ __forceinline__ void mma8(float c[4], unsigned a0, unsigned a1, unsigned a2,
                                     unsigned a3, unsigned b0, unsigned b1) {
    asm volatile(
        "mma.sync.aligned.m16n8k8.row.col.f32.tf32.tf32.f32 "
        "{%0,%1,%2,%3},{%4,%5,%6,%7},{%8,%9},{%0,%1,%2,%3};"
        : "+f"(c[0]), "+f"(c[1]), "+f"(c[2]), "+f"(c[3])
        : "r"(a0), "r"(a1), "r"(a2), "r"(a3), "r"(b0), "r"(b1));
}

// ---------------- CSR build ----------------
__global__ void hist_k(const int* __restrict__ dst) {
    int i = blockIdx.x * blockDim.x + threadIdx.x;
    if (i < NSB) g_lb[i] = 0;
    if (i < 4 * HIDD) g_tap[i] = 0.f;
    if (i < NE) atomicAdd(&g_deg[dst[i]], 1);
}

// single-kernel exclusive scan of g_deg via decoupled lookback
__global__ __launch_bounds__(256) void scan_lb_k() {
    __shared__ int warpsum[8];
    __shared__ int s_prefix;
    const int b = blockIdx.x, t = threadIdx.x;
    const int lane = t & 31, wid = t >> 5;
    const int i = b * 256 + t;
    int d = (i < NN) ? g_deg[i] : 0;

    int v = d;
#pragma unroll
    for (int o = 1; o < 32; o <<= 1) {
        int u = __shfl_up_sync(0xffffffffu, v, o);
        if (lane >= o) v += u;
    }
    if (lane == 31) warpsum[wid] = v;
    __syncthreads();
    if (t < 8) {
        int wv = warpsum[t];
#pragma unroll
        for (int o = 1; o < 8; o <<= 1) {
            int u = __shfl_up_sync(0xffu, wv, o);
            if (t >= o) wv += u;
        }
        warpsum[t] = wv;
    }
    __syncthreads();
    const int incl = v + (wid ? warpsum[wid - 1] : 0);
    const int total = warpsum[7];

    if (t == 0) {
        if (b == 0) atomicExch(&g_lb[0], ST_INC | total);
        else        atomicExch(&g_lb[b], ST_AGG | total);
    }

    if (wid == 0) {
        int prefix = 0;
        if (b > 0) {
            int idx = b - 1;
            while (true) {
                int j = idx - lane;
                int w = (j >= 0) ? atomicAdd(&g_lb[j], 0) : (ST_INC | 0);
                if (!__all_sync(0xffffffffu, w != 0)) continue;
                unsigned incmask = __ballot_sync(0xffffffffu, (w & ST_INC) != 0);
                if (incmask) {
                    int first = __ffs(incmask) - 1;
                    int contrib = (lane <= first) ? (w & VALMASK) : 0;
#pragma unroll
                    for (int o = 16; o; o >>= 1) contrib += __shfl_xor_sync(0xffffffffu, contrib, o);
                    prefix += contrib;
                    break;
                } else {
                    int contrib = w & VALMASK;
#pragma unroll
                    for (int o = 16; o; o >>= 1) contrib += __shfl_xor_sync(0xffffffffu, contrib, o);
                    prefix += contrib;
                    idx -= 32;
                }
            }
            if (lane == 0) atomicExch(&g_lb[b], ST_INC | (prefix + total));
        }
        if (lane == 0) s_prefix = prefix;
    }
    __syncthreads();
    int rp = s_prefix + incl - d;
    if (i < NN) { g_rowptr[i] = rp; g_cursor[i] = rp; }
    if (i == NN - 1) g_rowptr[NN] = NE;
}

__global__ void scatter_k(const int* __restrict__ src, const int* __restrict__ dst) {
    int i = blockIdx.x * blockDim.x + threadIdx.x;
    if (i < NE) {
        int d = dst[i];
        int pos = atomicAdd(&g_cursor[d], 1);
        g_esrc[pos] = src[i];
    }
}

// ---------------- fully fused persistent GIN layer ----------------
// 512 threads, 16 warps, warp tile m32 x n32. Per tile: gather(+self) from Xin
// -> tf32 smem -> GEMM1(BN,ReLU) -> GEMM2(ReLU) -> Xout + tap sums.
// Weights resident in smem for the whole kernel.
__global__ __launch_bounds__(512, 1) void gin_layer(
    const float* __restrict__ Xin, float* __restrict__ Xout, int tap_off,
    const float* __restrict__ W1, const float* __restrict__ b1,
    const float* __restrict__ gam, const float* __restrict__ bet,
    const float* __restrict__ mu, const float* __restrict__ var,
    const float* __restrict__ W2, const float* __restrict__ b2)
{
    extern __shared__ unsigned sm[];
    unsigned* sW1 = sm;                    // 128 x AS tf32 (BN-folded W1)
    unsigned* sW2 = sm + 128 * AS;         // 128 x AS tf32 W2
    unsigned* sA  = sm + 2 * 128 * AS;     // 128 x AS tf32 tile (A, then H1)
    float* sB1    = (float*)(sm + 3 * 128 * AS);
    float* sB2    = sB1 + 128;
    float* sTap   = sB2 + 128;
    float* sScale = sTap + 128;

    float* tap = g_tap + tap_off;

    const int tid = threadIdx.x;
    const int w = tid >> 5, lane = tid & 31;

    if (tid < 128) {
        float sc = gam[tid] * rsqrtf(var[tid] + 1e-5f);
        sScale[tid] = sc;
        sTap[tid] = 0.f;
        sB2[tid] = b2[tid];
        sB1[tid] = (b1[tid] - mu[tid]) * sc + bet[tid];
    }
    __syncthreads();   // sScale visible for weight fold

    // --- load both weight matrices once (float4, f2t) ---
    const float4* W14 = (const float4*)W1;
    const float4* W24 = (const float4*)W2;
    for (int idx = tid; idx < 4096; idx += 512) {
        int c = idx >> 5, k4 = (idx & 31) * 4;
        float s = sScale[c];
        float4 v1 = W14[idx];
        *(uint4*)&sW1[c * AS + k4] =
            make_uint4(f2t(v1.x * s), f2t(v1.y * s), f2t(v1.z * s), f2t(v1.w * s));
        float4 v2 = W24[idx];
        *(uint4*)&sW2[c * AS + k4] =
            make_uint4(f2t(v2.x), f2t(v2.y), f2t(v2.z), f2t(v2.w));
    }
    // (first in-loop __syncthreads covers weight visibility)

    // warp tiling: 16 warps = 4 row-tiles x 4 col-strips
    const int wr = w & 3, wc = w >> 2;
    const int rb = wr * 32, cb = wc * 32;
    const int gq = lane >> 2, q = lane & 3;

    // per-thread tap accumulators across all tiles
    float tS0[4], tS1[4];
#pragma unroll
    for (int nt = 0; nt < 4; nt++) { tS0[nt] = 0.f; tS1[nt] = 0.f; }

    const float4* X4 = (const float4*)Xin;

    for (int tile = blockIdx.x; tile < NB; tile += gridDim.x) {
        const int rowBase = tile * 128;

        // --- gather: warp w owns rows w*8 .. w*8+7 of the tile ---
        for (int i = 0; i < 8; i++) {
            int lr = w * 8 + i;
            int n = rowBase + lr;
            float4 acc = make_float4(0.f, 0.f, 0.f, 0.f);
            if (n < NN) {
                acc = X4[(size_t)n * 32 + lane];       // +x_i (eps=0 GIN)
                int e = g_rowptr[n], e1 = g_rowptr[n + 1];
                for (; e + 8 <= e1; e += 8) {
                    int s0 = g_esrc[e],     s1 = g_esrc[e + 1];
                    int s2 = g_esrc[e + 2], s3 = g_esrc[e + 3];
                    int s4 = g_esrc[e + 4], s5 = g_esrc[e + 5];
                    int s6 = g_esrc[e + 6], s7 = g_esrc[e + 7];
                    float4 v0 = X4[(size_t)s0 * 32 + lane];
                    float4 v1 = X4[(size_t)s1 * 32 + lane];
                    float4 v2 = X4[(size_t)s2 * 32 + lane];
                    float4 v3 = X4[(size_t)s3 * 32 + lane];
                    float4 v4 = X4[(size_t)s4 * 32 + lane];
                    float4 v5 = X4[(size_t)s5 * 32 + lane];
                    float4 v6 = X4[(size_t)s6 * 32 + lane];
                    float4 v7 = X4[(size_t)s7 * 32 + lane];
                    acc.x += ((v0.x + v1.x) + (v2.x + v3.x)) + ((v4.x + v5.x) + (v6.x + v7.x));
                    acc.y += ((v0.y + v1.y) + (v2.y + v3.y)) + ((v4.y + v5.y) + (v6.y + v7.y));
                    acc.z += ((v0.z + v1.z) + (v2.z + v3.z)) + ((v4.z + v5.z) + (v6.z + v7.z));
                    acc.w += ((v0.w + v1.w) + (v2.w + v3.w)) + ((v4.w + v5.w) + (v6.w + v7.w));
                }
                for (; e + 2 <= e1; e += 2) {
                    int s0 = g_esrc[e], s1 = g_esrc[e + 1];
                    float4 v0 = X4[(size_t)s0 * 32 + lane];
                    float4 v1 = X4[(size_t)s1 * 32 + lane];
                    acc.x += v0.x + v1.x;
                    acc.y += v0.y + v1.y;
                    acc.z += v0.z + v1.z;
                    acc.w += v0.w + v1.w;
                }
                if (e < e1) {
                    float4 v = X4[(size_t)g_esrc[e] * 32 + lane];
                    acc.x += v.x; acc.y += v.y; acc.z += v.z; acc.w += v.w;
                }
            }
            *(uint4*)&sA[lr * AS + lane * 4] =
                make_uint4(f2t(acc.x), f2t(acc.y), f2t(acc.z), f2t(acc.w));
        }
        __syncthreads();

        // --- GEMM1: H1 = ReLU(A @ W1'^T + b1') ---
        float acc1[2][4][4];
#pragma unroll
        for (int rt = 0; rt < 2; rt++)
#pragma unroll
            for (int nt = 0; nt < 4; nt++)
#pragma unroll
                for (int j = 0; j < 4; j++) acc1[rt][nt][j] = 0.f;

#pragma unroll
        for (int kt = 0; kt < 16; kt++) {
            int k0 = kt * 8 + q;
            unsigned a00 = sA[(rb + gq) * AS + k0];
            unsigned a01 = sA[(rb + gq) * AS + k0 + 4];
            unsigned a10 = sA[(rb + 8 + gq) * AS + k0];
            unsigned a11 = sA[(rb + 8 + gq) * AS + k0 + 4];
            unsigned a20 = sA[(rb + 16 + gq) * AS + k0];
            unsigned a21 = sA[(rb + 16 + gq) * AS + k0 + 4];
            unsigned a30 = sA[(rb + 24 + gq) * AS + k0];
            unsigned a31 = sA[(rb + 24 + gq) * AS + k0 + 4];
#pragma unroll
            for (int nt = 0; nt < 4; nt++) {
                int n0 = cb + nt * 8 + gq;
                unsigned b0 = sW1[n0 * AS + k0];
                unsigned b1v = sW1[n0 * AS + k0 + 4];
                mma8(acc1[0][nt], a00, a10, a01, a11, b0, b1v);
                mma8(acc1[1][nt], a20, a30, a21, a31, b0, b1v);
            }
        }
        __syncthreads();

        // --- H1 -> sA (tf32) ---
#pragma unroll
        for (int rt = 0; rt < 2; rt++) {
            int r0 = rb + 16 * rt + gq;
#pragma unroll
            for (int nt = 0; nt < 4; nt++) {
                int c0 = cb + nt * 8 + q * 2;
                float o00 = fmaxf(acc1[rt][nt][0] + sB1[c0], 0.f);
                float o01 = fmaxf(acc1[rt][nt][1] + sB1[c0 + 1], 0.f);
                float o10 = fmaxf(acc1[rt][nt][2] + sB1[c0], 0.f);
                float o11 = fmaxf(acc1[rt][nt][3] + sB1[c0 + 1], 0.f);
                *(uint2*)&sA[r0 * AS + c0] = make_uint2(f2t(o00), f2t(o01));
                *(uint2*)&sA[(r0 + 8) * AS + c0] = make_uint2(f2t(o10), f2t(o11));
            }
        }
        __syncthreads();

        // --- GEMM2: H2 = ReLU(H1 @ W2^T + b2) ---
        float acc2[2][4][4];
#pragma unroll
        for (int rt = 0; rt < 2; rt++)
#pragma unroll
            for (int nt = 0; nt < 4; nt++)
#pragma unroll
                for (int j = 0; j < 4; j++) acc2[rt][nt][j] = 0.f;

#pragma unroll
        for (int kt = 0; kt < 16; kt++) {
            int k0 = kt * 8 + q;
            unsigned a00 = sA[(rb + gq) * AS + k0];
            unsigned a01 = sA[(rb + gq) * AS + k0 + 4];
            unsigned a10 = sA[(rb + 8 + gq) * AS + k0];
            unsigned a11 = sA[(rb + 8 + gq) * AS + k0 + 4];
            unsigned a20 = sA[(rb + 16 + gq) * AS + k0];
            unsigned a21 = sA[(rb + 16 + gq) * AS + k0 + 4];
            unsigned a30 = sA[(rb + 24 + gq) * AS + k0];
            unsigned a31 = sA[(rb + 24 + gq) * AS + k0 + 4];
#pragma unroll
            for (int nt = 0; nt < 4; nt++) {
                int n0 = cb + nt * 8 + gq;
                unsigned b0 = sW2[n0 * AS + k0];
                unsigned b1v = sW2[n0 * AS + k0 + 4];
                mma8(acc2[0][nt], a00, a10, a01, a11, b0, b1v);
                mma8(acc2[1][nt], a20, a30, a21, a31, b0, b1v);
            }
        }

        // --- epilogue: write Xout, accumulate tap in regs ---
#pragma unroll
        for (int rt = 0; rt < 2; rt++) {
            int r0 = rowBase + rb + 16 * rt + gq;
            int r1 = r0 + 8;
            bool m0v = (r0 < NN), m1v = (r1 < NN);
#pragma unroll
            for (int nt = 0; nt < 4; nt++) {
                int c0 = cb + nt * 8 + q * 2;
                float o00 = m0v ? fmaxf(acc2[rt][nt][0] + sB2[c0], 0.f) : 0.f;
                float o01 = m0v ? fmaxf(acc2[rt][nt][1] + sB2[c0 + 1], 0.f) : 0.f;
                float o10 = m1v ? fmaxf(acc2[rt][nt][2] + sB2[c0], 0.f) : 0.f;
                float o11 = m1v ? fmaxf(acc2[rt][nt][3] + sB2[c0 + 1], 0.f) : 0.f;
                if (m0v) *(float2*)&Xout[(size_t)r0 * 128 + c0] = make_float2(o00, o01);
                if (m1v) *(float2*)&Xout[(size_t)r1 * 128 + c0] = make_float2(o10, o11);
                tS0[nt] += o00 + o10;
                tS1[nt] += o01 + o11;
            }
        }
        __syncthreads();   // sA reuse next tile
    }

    // --- final tap reduction: shuffle across gq lanes, then smem, then global ---
#pragma unroll
    for (int nt = 0; nt < 4; nt++) {
        float t0 = tS0[nt], t1 = tS1[nt];
#pragma unroll
        for (int o = 16; o >= 4; o >>= 1) {
            t0 += __shfl_xor_sync(0xffffffffu, t0, o);
            t1 += __shfl_xor_sync(0xffffffffu, t1, o);
        }
        if (gq == 0) {
            int c0 = cb + nt * 8 + q * 2;
            atomicAdd(&sTap[c0], t0);
            atomicAdd(&sTap[c0 + 1], t1);
        }
    }
    __syncthreads();
    if (tid < 128) atomicAdd(&tap[tid], sTap[tid]);
}

// ---------------- readout ----------------
__global__ void readout_k(const float* __restrict__ Wll, const float* __restrict__ bll,
                          float* __restrict__ out) {
    int w = threadIdx.x >> 5, lane = threadIdx.x & 31;
    if (w < 10) {
        float s = 0.f;
        for (int k = lane; k < 512; k += 32) s += g_tap[k] * Wll[w * 512 + k];
#pragma unroll
        for (int off = 16; off; off >>= 1) s += __shfl_xor_sync(0xffffffffu, s, off);
        if (lane == 0) out[w] = s + bll[w];
    }
}

// ---------------- host ----------------
extern "C" void kernel_launch(void* const* d_in, const int* in_sizes, int n_in,
                              void* d_out, int out_size) {
    const float* x   = (const float*)d_in[0];
    const int*   ei  = (const int*)d_in[1];
    const float* W1_0 = (const float*)d_in[2];
    const float* b1_0 = (const float*)d_in[3];
    const float* g0   = (const float*)d_in[4];
    const float* be0  = (const float*)d_in[5];
    const float* m0   = (const float*)d_in[6];
    const float* v0   = (const float*)d_in[7];
    const float* W2_0 = (const float*)d_in[8];
    const float* b2_0 = (const float*)d_in[9];
    const float* W1s  = (const float*)d_in[10];
    const float* b1s  = (const float*)d_in[11];
    const float* gs   = (const float*)d_in[12];
    const float* bes  = (const float*)d_in[13];
    const float* ms   = (const float*)d_in[14];
    const float* vs   = (const float*)d_in[15];
    const float* W2s  = (const float*)d_in[16];
    const float* b2s  = (const float*)d_in[17];
    const float* Wll  = (const float*)d_in[18];
    const float* bll  = (const float*)d_in[19];
    float* out = (float*)d_out;

    cudaFuncSetAttribute(gin_layer, cudaFuncAttributeMaxDynamicSharedMemorySize, SMEM_BYTES);

    const int* esrc_in = ei;        // edge_index[0] = src
    const int* edst_in = ei + NE;   // edge_index[1] = dst

    void* dDeg; cudaGetSymbolAddress(&dDeg, g_deg);
    cudaMemsetAsync(dDeg, 0, NN * sizeof(int), 0);

    hist_k<<<(NE + 255) / 256, 256>>>(edst_in);
    scan_lb_k<<<NSB, 256>>>();
    scatter_k<<<(NE + 255) / 256, 256>>>(esrc_in, edst_in);

    float* dx1; cudaGetSymbolAddress((void**)&dx1, g_x1);
    float* dx2; cudaGetSymbolAddress((void**)&dx2, g_x2);

    // fused gather+MLP per layer
    gin_layer<<<PGRID, 512, SMEM_BYTES>>>(x, dx1, 0,
                                          W1_0, b1_0, g0, be0, m0, v0, W2_0, b2_0);
    for (int i = 1; i < 4; i++) {
        const float* Xin = (i % 2 == 1) ? dx1 : dx2;
        float* Xo = (i % 2 == 1) ? dx2 : dx1;
        int off = i - 1;
        gin_layer<<<PGRID, 512, SMEM_BYTES>>>(Xin, Xo, i * 128,
                                              W1s + off * 16384, b1s + off * 128,
                                              gs + off * 128, bes + off * 128,
                                              ms + off * 128, vs + off * 128,
                                              W2s + off * 16384, b2s + off * 128);
    }
    readout_k<<<1, 320>>>(Wll, bll, out);
}

// round 7
// speedup vs baseline: 1.3120x; 1.3120x over previous
#include <cuda_runtime.h>
#include <cuda_fp16.h>
#include <cstdint>

#define NN 50000
#define NE 600000
#define HIDD 128
#define AS 132                       // padded row stride (floats): conflict-free
#define SMEM_WORDS (3*128*AS + 4*128)
#define SMEM_BYTES (SMEM_WORDS*4)    // 204800 B
#define NB ((NN + 127) / 128)        // 391 tiles
#define NSB ((NN + 255) / 256)       // scan blocks (196)
#define PGRID 148                    // persistent grid

#define ST_AGG (1 << 30)
#define ST_INC (2 << 30)
#define VALMASK 0x3FFFFFFF

// ---------------- device scratch (static, no runtime alloc) ----------------
__device__ __align__(16) __half g_h0[(size_t)NN * HIDD];   // fp16 x
__device__ __align__(16) __half g_h1[(size_t)NN * HIDD];   // fp16 activations
__device__ __align__(16) __half g_h2[(size_t)NN * HIDD];
__device__ __align__(16) float  g_agg[(size_t)NN * HIDD];  // fp32 aggregate
__device__ int   g_deg[NN];
__device__ int   g_rowptr[NN + 1];
__device__ int   g_cursor[NN];
__device__ int   g_esrc[NE];
__device__ int   g_lb[NSB];
__device__ float g_tap[4 * HIDD];

// ---------------- helpers ----------------
__device__ __forceinline__ unsigned f2t(float f) {
    unsigned u;
    asm("cvt.rna.tf32.f32 %0, %1;" : "=r"(u) : "f"(f));
    return u;
}

__device__ __forceinline__ void mma8(float c[4], unsigned a0, unsigned a1, unsigned a2,
                                     unsigned a3, unsigned b0, unsigned b1) {
    asm volatile(
        "mma.sync.aligned.m16n8k8.row.col.f32.tf32.tf32.f32 "
        "{%0,%1,%2,%3},{%4,%5,%6,%7},{%8,%9},{%0,%1,%2,%3};"
        : "+f"(c[0]), "+f"(c[1]), "+f"(c[2]), "+f"(c[3])
        : "r"(a0), "r"(a1), "r"(a2), "r"(a3), "r"(b0), "r"(b1));
}

__device__ __forceinline__ void h2acc(float4& acc, uint2 v) {
    float2 f0 = __half22float2(*(__half2*)&v.x);
    float2 f1 = __half22float2(*(__half2*)&v.y);
    acc.x += f0.x; acc.y += f0.y; acc.z += f1.x; acc.w += f1.y;
}

// ---------------- CSR build ----------------
__global__ void hist_k(const int* __restrict__ dst) {
    int i = blockIdx.x * blockDim.x + threadIdx.x;
    if (i < NSB) g_lb[i] = 0;
    if (i < 4 * HIDD) g_tap[i] = 0.f;
    if (i < NE) atomicAdd(&g_deg[dst[i]], 1);
}

// single-kernel exclusive scan of g_deg via decoupled lookback
__global__ __launch_bounds__(256) void scan_lb_k() {
    __shared__ int warpsum[8];
    __shared__ int s_prefix;
    const int b = blockIdx.x, t = threadIdx.x;
    const int lane = t & 31, wid = t >> 5;
    const int i = b * 256 + t;
    int d = (i < NN) ? g_deg[i] : 0;

    int v = d;
#pragma unroll
    for (int o = 1; o < 32; o <<= 1) {
        int u = __shfl_up_sync(0xffffffffu, v, o);
        if (lane >= o) v += u;
    }
    if (lane == 31) warpsum[wid] = v;
    __syncthreads();
    if (t < 8) {
        int wv = warpsum[t];
#pragma unroll
        for (int o = 1; o < 8; o <<= 1) {
            int u = __shfl_up_sync(0xffu, wv, o);
            if (t >= o) wv += u;
        }
        warpsum[t] = wv;
    }
    __syncthreads();
    const int incl = v + (wid ? warpsum[wid - 1] : 0);
    const int total = warpsum[7];

    if (t == 0) {
        if (b == 0) atomicExch(&g_lb[0], ST_INC | total);
        else        atomicExch(&g_lb[b], ST_AGG | total);
    }

    if (wid == 0) {
        int prefix = 0;
        if (b > 0) {
            int idx = b - 1;
            while (true) {
                int j = idx - lane;
                int w = (j >= 0) ? atomicAdd(&g_lb[j], 0) : (ST_INC | 0);
                if (!__all_sync(0xffffffffu, w != 0)) continue;
                unsigned incmask = __ballot_sync(0xffffffffu, (w & ST_INC) != 0);
                if (incmask) {
                    int first = __ffs(incmask) - 1;
                    int contrib = (lane <= first) ? (w & VALMASK) : 0;
#pragma unroll
                    for (int o = 16; o; o >>= 1) contrib += __shfl_xor_sync(0xffffffffu, contrib, o);
                    prefix += contrib;
                    break;
                } else {
                    int contrib = w & VALMASK;
#pragma unroll
                    for (int o = 16; o; o >>= 1) contrib += __shfl_xor_sync(0xffffffffu, contrib, o);
                    prefix += contrib;
                    idx -= 32;
                }
            }
            if (lane == 0) atomicExch(&g_lb[b], ST_INC | (prefix + total));
        }
        if (lane == 0) s_prefix = prefix;
    }
    __syncthreads();
    int rp = s_prefix + incl - d;
    if (i < NN) { g_rowptr[i] = rp; g_cursor[i] = rp; }
    if (i == NN - 1) g_rowptr[NN] = NE;
}

// scatter + fp32->fp16 conversion of x (fused to save a launch)
__global__ void scatter_k(const int* __restrict__ src, const int* __restrict__ dst,
                          const float* __restrict__ x) {
    int i = blockIdx.x * blockDim.x + threadIdx.x;
    if (i < NE) {
        int d = dst[i];
        int pos = atomicAdd(&g_cursor[d], 1);
        g_esrc[pos] = src[i];
    }
    const float2* x2 = (const float2*)x;
    __half2* h2 = (__half2*)g_h0;
    const int total = NN * HIDD / 2;           // 3.2M half2
    for (int j = i; j < total; j += NE) {
        float2 v = x2[j];
        h2[j] = __floats2half2_rn(v.x, v.y);
    }
}

// ---------------- aggregation: warp per node, fp16 rows, fp32 accum ----------------
__global__ __launch_bounds__(256) void agg_k(const __half* __restrict__ Xin) {
    int gw = (blockIdx.x * blockDim.x + threadIdx.x) >> 5;
    int lane = threadIdx.x & 31;
    if (gw >= NN) return;
    const uint2* X2 = (const uint2*)Xin;       // 32 uint2 (8B) per 128-half row
    float4 acc = make_float4(0.f, 0.f, 0.f, 0.f);
    h2acc(acc, X2[(size_t)gw * 32 + lane]);    // +x_i (eps=0 GIN)
    int e = g_rowptr[gw], e1 = g_rowptr[gw + 1];
    for (; e + 8 <= e1; e += 8) {
        int s0 = g_esrc[e],     s1 = g_esrc[e + 1];
        int s2 = g_esrc[e + 2], s3 = g_esrc[e + 3];
        int s4 = g_esrc[e + 4], s5 = g_esrc[e + 5];
        int s6 = g_esrc[e + 6], s7 = g_esrc[e + 7];
        uint2 v0 = X2[(size_t)s0 * 32 + lane];
        uint2 v1 = X2[(size_t)s1 * 32 + lane];
        uint2 v2 = X2[(size_t)s2 * 32 + lane];
        uint2 v3 = X2[(size_t)s3 * 32 + lane];
        uint2 v4 = X2[(size_t)s4 * 32 + lane];
        uint2 v5 = X2[(size_t)s5 * 32 + lane];
        uint2 v6 = X2[(size_t)s6 * 32 + lane];
        uint2 v7 = X2[(size_t)s7 * 32 + lane];
        h2acc(acc, v0); h2acc(acc, v1); h2acc(acc, v2); h2acc(acc, v3);
        h2acc(acc, v4); h2acc(acc, v5); h2acc(acc, v6); h2acc(acc, v7);
    }
    for (; e + 2 <= e1; e += 2) {
        uint2 v0 = X2[(size_t)g_esrc[e] * 32 + lane];
        uint2 v1 = X2[(size_t)g_esrc[e + 1] * 32 + lane];
        h2acc(acc, v0); h2acc(acc, v1);
    }
    if (e < e1) h2acc(acc, X2[(size_t)g_esrc[e] * 32 + lane]);
    ((float4*)g_agg)[(size_t)gw * 32 + lane] = acc;
}

// ---------------- persistent fused GIN MLP layer (reads g_agg) ----------------
// 512 threads, 16 warps, warp tile m32 x n32. Weights resident in smem.
// Writes fp16 activations for the next layer's gather.
__global__ __launch_bounds__(512, 1) void gin_layer(
    __half* __restrict__ Xout, int tap_off,
    const float* __restrict__ W1, const float* __restrict__ b1,
    const float* __restrict__ gam, const float* __restrict__ bet,
    const float* __restrict__ mu, const float* __restrict__ var,
    const float* __restrict__ W2, const float* __restrict__ b2)
{
    extern __shared__ unsigned sm[];
    unsigned* sW1 = sm;                    // 128 x AS tf32 (BN-folded W1)
    unsigned* sW2 = sm + 128 * AS;         // 128 x AS tf32 W2
    unsigned* sA  = sm + 2 * 128 * AS;     // 128 x AS tf32 tile (A, then H1)
    float* sB1    = (float*)(sm + 3 * 128 * AS);
    float* sB2    = sB1 + 128;
    float* sTap   = sB2 + 128;
    float* sScale = sTap + 128;

    float* tap = g_tap + tap_off;

    const int tid = threadIdx.x;
    const int w = tid >> 5, lane = tid & 31;

    if (tid < 128) {
        float sc = gam[tid] * rsqrtf(var[tid] + 1e-5f);
        sScale[tid] = sc;
        sTap[tid] = 0.f;
        sB2[tid] = b2[tid];
        sB1[tid] = (b1[tid] - mu[tid]) * sc + bet[tid];
    }
    __syncthreads();   // sScale visible for weight fold

    // --- load both weight matrices once (float4, f2t) ---
    const float4* W14 = (const float4*)W1;
    const float4* W24 = (const float4*)W2;
    for (int idx = tid; idx < 4096; idx += 512) {
        int c = idx >> 5, k4 = (idx & 31) * 4;
        float s = sScale[c];
        float4 v1 = W14[idx];
        *(uint4*)&sW1[c * AS + k4] =
            make_uint4(f2t(v1.x * s), f2t(v1.y * s), f2t(v1.z * s), f2t(v1.w * s));
        float4 v2 = W24[idx];
        *(uint4*)&sW2[c * AS + k4] =
            make_uint4(f2t(v2.x), f2t(v2.y), f2t(v2.z), f2t(v2.w));
    }
    // (first in-loop __syncthreads covers weight visibility)

    // warp tiling: 16 warps = 4 row-tiles x 4 col-strips
    const int wr = w & 3, wc = w >> 2;
    const int rb = wr * 32, cb = wc * 32;
    const int gq = lane >> 2, q = lane & 3;

    float tS0[4], tS1[4];
#pragma unroll
    for (int nt = 0; nt < 4; nt++) { tS0[nt] = 0.f; tS1[nt] = 0.f; }

    const float4* A4 = (const float4*)g_agg;

    for (int tile = blockIdx.x; tile < NB; tile += gridDim.x) {
        const int rowBase = tile * 128;

        // --- A tile from g_agg (float4) ---
        for (int idx = tid; idx < 4096; idx += 512) {
            int r = idx >> 5, c4 = idx & 31;
            int n = rowBase + r;
            float4 v = make_float4(0.f, 0.f, 0.f, 0.f);
            if (n < NN) v = A4[(size_t)n * 32 + c4];
            *(uint4*)&sA[r * AS + c4 * 4] =
                make_uint4(f2t(v.x), f2t(v.y), f2t(v.z), f2t(v.w));
        }
        __syncthreads();

        // --- GEMM1: H1 = ReLU(A @ W1'^T + b1') ---
        float acc1[2][4][4];
#pragma unroll
        for (int rt = 0; rt < 2; rt++)
#pragma unroll
            for (int nt = 0; nt < 4; nt++)
#pragma unroll
                for (int j = 0; j < 4; j++) acc1[rt][nt][j] = 0.f;

#pragma unroll
        for (int kt = 0; kt < 16; kt++) {
            int k0 = kt * 8 + q;
            unsigned a00 = sA[(rb + gq) * AS + k0];
            unsigned a01 = sA[(rb + gq) * AS + k0 + 4];
            unsigned a10 = sA[(rb + 8 + gq) * AS + k0];
            unsigned a11 = sA[(rb + 8 + gq) * AS + k0 + 4];
            unsigned a20 = sA[(rb + 16 + gq) * AS + k0];
            unsigned a21 = sA[(rb + 16 + gq) * AS + k0 + 4];
            unsigned a30 = sA[(rb + 24 + gq) * AS + k0];
            unsigned a31 = sA[(rb + 24 + gq) * AS + k0 + 4];
#pragma unroll
            for (int nt = 0; nt < 4; nt++) {
                int n0 = cb + nt * 8 + gq;
                unsigned b0 = sW1[n0 * AS + k0];
                unsigned b1v = sW1[n0 * AS + k0 + 4];
                mma8(acc1[0][nt], a00, a10, a01, a11, b0, b1v);
                mma8(acc1[1][nt], a20, a30, a21, a31, b0, b1v);
            }
        }
        __syncthreads();

        // --- H1 -> sA (tf32) ---
#pragma unroll
        for (int rt = 0; rt < 2; rt++) {
            int r0 = rb + 16 * rt + gq;
#pragma unroll
            for (int nt = 0; nt < 4; nt++) {
                int c0 = cb + nt * 8 + q * 2;
                float o00 = fmaxf(acc1[rt][nt][0] + sB1[c0], 0.f);
                float o01 = fmaxf(acc1[rt][nt][1] + sB1[c0 + 1], 0.f);
                float o10 = fmaxf(acc1[rt][nt][2] + sB1[c0], 0.f);
                float o11 = fmaxf(acc1[rt][nt][3] + sB1[c0 + 1], 0.f);
                *(uint2*)&sA[r0 * AS + c0] = make_uint2(f2t(o00), f2t(o01));
                *(uint2*)&sA[(r0 + 8) * AS + c0] = make_uint2(f2t(o10), f2t(o11));
            }
        }
        __syncthreads();

        // --- GEMM2: H2 = ReLU(H1 @ W2^T + b2) ---
        float acc2[2][4][4];
#pragma unroll
        for (int rt = 0; rt < 2; rt++)
#pragma unroll
            for (int nt = 0; nt < 4; nt++)
#pragma unroll
                for (int j = 0; j < 4; j++) acc2[rt][nt][j] = 0.f;

#pragma unroll
        for (int kt = 0; kt < 16; kt++) {
            int k0 = kt * 8 + q;
            unsigned a00 = sA[(rb + gq) * AS + k0];
            unsigned a01 = sA[(rb + gq) * AS + k0 + 4];
            unsigned a10 = sA[(rb + 8 + gq) * AS + k0];
            unsigned a11 = sA[(rb + 8 + gq) * AS + k0 + 4];
            unsigned a20 = sA[(rb + 16 + gq) * AS + k0];
            unsigned a21 = sA[(rb + 16 + gq) * AS + k0 + 4];
            unsigned a30 = sA[(rb + 24 + gq) * AS + k0];
            unsigned a31 = sA[(rb + 24 + gq) * AS + k0 + 4];
#pragma unroll
            for (int nt = 0; nt < 4; nt++) {
                int n0 = cb + nt * 8 + gq;
                unsigned b0 = sW2[n0 * AS + k0];
                unsigned b1v = sW2[n0 * AS + k0 + 4];
                mma8(acc2[0][nt], a00, a10, a01, a11, b0, b1v);
                mma8(acc2[1][nt], a20, a30, a21, a31, b0, b1v);
            }
        }

        // --- epilogue: write fp16 Xout, accumulate tap in fp32 regs ---
#pragma unroll
        for (int rt = 0; rt < 2; rt++) {
            int r0 = rowBase + rb + 16 * rt + gq;
            int r1 = r0 + 8;
            bool m0v = (r0 < NN), m1v = (r1 < NN);
#pragma unroll
            for (int nt = 0; nt < 4; nt++) {
                int c0 = cb + nt * 8 + q * 2;
                float o00 = m0v ? fmaxf(acc2[rt][nt][0] + sB2[c0], 0.f) : 0.f;
                float o01 = m0v ? fmaxf(acc2[rt][nt][1] + sB2[c0 + 1], 0.f) : 0.f;
                float o10 = m1v ? fmaxf(acc2[rt][nt][2] + sB2[c0], 0.f) : 0.f;
                float o11 = m1v ? fmaxf(acc2[rt][nt][3] + sB2[c0 + 1], 0.f) : 0.f;
                if (m0v) *(__half2*)&Xout[(size_t)r0 * 128 + c0] = __floats2half2_rn(o00, o01);
                if (m1v) *(__half2*)&Xout[(size_t)r1 * 128 + c0] = __floats2half2_rn(o10, o11);
                tS0[nt] += o00 + o10;
                tS1[nt] += o01 + o11;
            }
        }
        __syncthreads();   // sA reuse next tile
    }

    // --- final tap reduction ---
#pragma unroll
    for (int nt = 0; nt < 4; nt++) {
        float t0 = tS0[nt], t1 = tS1[nt];
#pragma unroll
        for (int o = 16; o >= 4; o >>= 1) {
            t0 += __shfl_xor_sync(0xffffffffu, t0, o);
            t1 += __shfl_xor_sync(0xffffffffu, t1, o);
        }
        if (gq == 0) {
            int c0 = cb + nt * 8 + q * 2;
            atomicAdd(&sTap[c0], t0);
            atomicAdd(&sTap[c0 + 1], t1);
        }
    }
    __syncthreads();
    if (tid < 128) atomicAdd(&tap[tid], sTap[tid]);
}

// ---------------- readout ----------------
__global__ void readout_k(const float* __restrict__ Wll, const float* __restrict__ bll,
                          float* __restrict__ out) {
    int w = threadIdx.x >> 5, lane = threadIdx.x & 31;
    if (w < 10) {
        float s = 0.f;
        for (int k = lane; k < 512; k += 32) s += g_tap[k] * Wll[w * 512 + k];
#pragma unroll
        for (int off = 16; off; off >>= 1) s += __shfl_xor_sync(0xffffffffu, s, off);
        if (lane == 0) out[w] = s + bll[w];
    }
}

// ---------------- host ----------------
extern "C" void kernel_launch(void* const* d_in, const int* in_sizes, int n_in,
                              void* d_out, int out_size) {
    const float* x   = (const float*)d_in[0];
    const int*   ei  = (const int*)d_in[1];
    const float* W1_0 = (const float*)d_in[2];
    const float* b1_0 = (const float*)d_in[3];
    const float* g0   = (const float*)d_in[4];
    const float* be0  = (const float*)d_in[5];
    const float* m0   = (const float*)d_in[6];
    const float* v0   = (const float*)d_in[7];
    const float* W2_0 = (const float*)d_in[8];
    const float* b2_0 = (const float*)d_in[9];
    const float* W1s  = (const float*)d_in[10];
    const float* b1s  = (const float*)d_in[11];
    const float* gs   = (const float*)d_in[12];
    const float* bes  = (const float*)d_in[13];
    const float* ms   = (const float*)d_in[14];
    const float* vs   = (const float*)d_in[15];
    const float* W2s  = (const float*)d_in[16];
    const float* b2s  = (const float*)d_in[17];
    const float* Wll  = (const float*)d_in[18];
    const float* bll  = (const float*)d_in[19];
    float* out = (float*)d_out;

    cudaFuncSetAttribute(gin_layer, cudaFuncAttributeMaxDynamicSharedMemorySize, SMEM_BYTES);

    const int* esrc_in = ei;        // edge_index[0] = src
    const int* edst_in = ei + NE;   // edge_index[1] = dst

    void* dDeg; cudaGetSymbolAddress(&dDeg, g_deg);
    cudaMemsetAsync(dDeg, 0, NN * sizeof(int), 0);

    hist_k<<<(NE + 255) / 256, 256>>>(edst_in);
    scan_lb_k<<<NSB, 256>>>();
    scatter_k<<<(NE + 255) / 256, 256>>>(esrc_in, edst_in, x);

    __half* dh0; cudaGetSymbolAddress((void**)&dh0, g_h0);
    __half* dh1; cudaGetSymbolAddress((void**)&dh1, g_h1);
    __half* dh2; cudaGetSymbolAddress((void**)&dh2, g_h2);

    const int aggGrid = (NN * 32 + 255) / 256;

    // layer i: agg(fp16 in) -> gin (g_agg fp32 -> fp16 out)
    const __half* ins[4]  = {dh0, dh1, dh2, dh1};
    __half*       outs[4] = {dh1, dh2, dh1, dh2};

    agg_k<<<aggGrid, 256>>>(ins[0]);
    gin_layer<<<PGRID, 512, SMEM_BYTES>>>(outs[0], 0,
                                          W1_0, b1_0, g0, be0, m0, v0, W2_0, b2_0);
    for (int i = 1; i < 4; i++) {
        int off = i - 1;
        agg_k<<<aggGrid, 256>>>(ins[i]);
        gin_layer<<<PGRID, 512, SMEM_BYTES>>>(outs[i], i * 128,
                                              W1s + off * 16384, b1s + off * 128,
                                              gs + off * 128, bes + off * 128,
                                              ms + off * 128, vs + off * 128,
                                              W2s + off * 16384, b2s + off * 128);
    }
    readout_k<<<1, 320>>>(Wll, bll, out);
}

// round 8
// speedup vs baseline: 1.6851x; 1.2844x over previous
#include <cuda_runtime.h>
#include <cuda_fp16.h>
#include <cstdint>

#define NN 50000
#define NE 600000
#define HIDD 128
#define AS2 136                      // padded row stride in halves: conflict-free
#define SMEM_BYTES (3 * 128 * AS2 * 2 + 2048)
#define NB ((NN + 127) / 128)        // 391 tiles
#define NSB ((NN + 255) / 256)       // scan blocks (196)
#define PGRID 148                    // persistent grid

#define ST_AGG (1 << 30)
#define ST_INC (2 << 30)
#define VALMASK 0x3FFFFFFF

// ---------------- device scratch (static, no runtime alloc) ----------------
__device__ __align__(16) __half g_h0[(size_t)NN * HIDD];   // fp16 x
__device__ __align__(16) __half g_h1[(size_t)NN * HIDD];   // fp16 activations
__device__ __align__(16) __half g_h2[(size_t)NN * HIDD];
__device__ __align__(16) __half g_agg[(size_t)NN * HIDD];  // fp16 aggregate
__device__ int   g_deg[NN];
__device__ int   g_rowptr[NN + 1];
__device__ int   g_cursor[NN];
__device__ int   g_esrc[NE];
__device__ int   g_lb[NSB];
__device__ float g_tap[4 * HIDD];

// ---------------- helpers ----------------
__device__ __forceinline__ void mma16(float c[4], unsigned a0, unsigned a1, unsigned a2,
                                      unsigned a3, unsigned b0, unsigned b1) {
    asm volatile(
        "mma.sync.aligned.m16n8k16.row.col.f32.f16.f16.f32 "
        "{%0,%1,%2,%3},{%4,%5,%6,%7},{%8,%9},{%0,%1,%2,%3};"
        : "+f"(c[0]), "+f"(c[1]), "+f"(c[2]), "+f"(c[3])
        : "r"(a0), "r"(a1), "r"(a2), "r"(a3), "r"(b0), "r"(b1));
}

__device__ __forceinline__ void h2acc(float4& acc, uint2 v) {
    float2 f0 = __half22float2(*(__half2*)&v.x);
    float2 f1 = __half22float2(*(__half2*)&v.y);
    acc.x += f0.x; acc.y += f0.y; acc.z += f1.x; acc.w += f1.y;
}

// pairwise: one fp16 add on the pair, then fp32 accumulate (fewer instructions)
__device__ __forceinline__ void h2pair(float4& acc, uint2 va, uint2 vb) {
    __half2 s0 = __hadd2(*(__half2*)&va.x, *(__half2*)&vb.x);
    __half2 s1 = __hadd2(*(__half2*)&va.y, *(__half2*)&vb.y);
    float2 f0 = __half22float2(s0);
    float2 f1 = __half22float2(s1);
    acc.x += f0.x; acc.y += f0.y; acc.z += f1.x; acc.w += f1.y;
}

// ---------------- CSR build ----------------
__global__ void hist_k(const int* __restrict__ dst) {
    int i = blockIdx.x * blockDim.x + threadIdx.x;
    if (i < NSB) g_lb[i] = 0;
    if (i < 4 * HIDD) g_tap[i] = 0.f;
    if (i < NE) atomicAdd(&g_deg[dst[i]], 1);
}

// single-kernel exclusive scan of g_deg via decoupled lookback
__global__ __launch_bounds__(256) void scan_lb_k() {
    __shared__ int warpsum[8];
    __shared__ int s_prefix;
    const int b = blockIdx.x, t = threadIdx.x;
    const int lane = t & 31, wid = t >> 5;
    const int i = b * 256 + t;
    int d = (i < NN) ? g_deg[i] : 0;

    int v = d;
#pragma unroll
    for (int o = 1; o < 32; o <<= 1) {
        int u = __shfl_up_sync(0xffffffffu, v, o);
        if (lane >= o) v += u;
    }
    if (lane == 31) warpsum[wid] = v;
    __syncthreads();
    if (t < 8) {
        int wv = warpsum[t];
#pragma unroll
        for (int o = 1; o < 8; o <<= 1) {
            int u = __shfl_up_sync(0xffu, wv, o);
            if (t >= o) wv += u;
        }
        warpsum[t] = wv;
    }
    __syncthreads();
    const int incl = v + (wid ? warpsum[wid - 1] : 0);
    const int total = warpsum[7];

    if (t == 0) {
        if (b == 0) atomicExch(&g_lb[0], ST_INC | total);
        else        atomicExch(&g_lb[b], ST_AGG | total);
    }

    if (wid == 0) {
        int prefix = 0;
        if (b > 0) {
            int idx = b - 1;
            while (true) {
                int j = idx - lane;
                int w = (j >= 0) ? atomicAdd(&g_lb[j], 0) : (ST_INC | 0);
                if (!__all_sync(0xffffffffu, w != 0)) continue;
                unsigned incmask = __ballot_sync(0xffffffffu, (w & ST_INC) != 0);
                if (incmask) {
                    int first = __ffs(incmask) - 1;
                    int contrib = (lane <= first) ? (w & VALMASK) : 0;
#pragma unroll
                    for (int o = 16; o; o >>= 1) contrib += __shfl_xor_sync(0xffffffffu, contrib, o);
                    prefix += contrib;
                    break;
                } else {
                    int contrib = w & VALMASK;
#pragma unroll
                    for (int o = 16; o; o >>= 1) contrib += __shfl_xor_sync(0xffffffffu, contrib, o);
                    prefix += contrib;
                    idx -= 32;
                }
            }
            if (lane == 0) atomicExch(&g_lb[b], ST_INC | (prefix + total));
        }
        if (lane == 0) s_prefix = prefix;
    }
    __syncthreads();
    int rp = s_prefix + incl - d;
    if (i < NN) { g_rowptr[i] = rp; g_cursor[i] = rp; }
    if (i == NN - 1) g_rowptr[NN] = NE;
}

// scatter + fp32->fp16 conversion of x
__global__ void scatter_k(const int* __restrict__ src, const int* __restrict__ dst,
                          const float* __restrict__ x) {
    int i = blockIdx.x * blockDim.x + threadIdx.x;
    if (i < NE) {
        int d = dst[i];
        int pos = atomicAdd(&g_cursor[d], 1);
        g_esrc[pos] = src[i];
    }
    const float2* x2 = (const float2*)x;
    __half2* h2 = (__half2*)g_h0;
    const int total = NN * HIDD / 2;
    for (int j = i; j < total; j += NE) {
        float2 v = x2[j];
        h2[j] = __floats2half2_rn(v.x, v.y);
    }
}

// ---------------- aggregation: warp per node, fp16 in/out, fp32 accum ----------------
__global__ __launch_bounds__(256) void agg_k(const __half* __restrict__ Xin) {
    int gw = (blockIdx.x * blockDim.x + threadIdx.x) >> 5;
    int lane = threadIdx.x & 31;
    if (gw >= NN) return;
    const uint2* X2 = (const uint2*)Xin;       // 32 uint2 (4 halves) per 128-half row
    float4 acc = make_float4(0.f, 0.f, 0.f, 0.f);
    h2acc(acc, X2[(size_t)gw * 32 + lane]);    // +x_i (eps=0 GIN)
    int e = g_rowptr[gw], e1 = g_rowptr[gw + 1];
    for (; e + 8 <= e1; e += 8) {
        int s0 = g_esrc[e],     s1 = g_esrc[e + 1];
        int s2 = g_esrc[e + 2], s3 = g_esrc[e + 3];
        int s4 = g_esrc[e + 4], s5 = g_esrc[e + 5];
        int s6 = g_esrc[e + 6], s7 = g_esrc[e + 7];
        uint2 v0 = X2[(size_t)s0 * 32 + lane];
        uint2 v1 = X2[(size_t)s1 * 32 + lane];
        uint2 v2 = X2[(size_t)s2 * 32 + lane];
        uint2 v3 = X2[(size_t)s3 * 32 + lane];
        uint2 v4 = X2[(size_t)s4 * 32 + lane];
        uint2 v5 = X2[(size_t)s5 * 32 + lane];
        uint2 v6 = X2[(size_t)s6 * 32 + lane];
        uint2 v7 = X2[(size_t)s7 * 32 + lane];
        h2pair(acc, v0, v1); h2pair(acc, v2, v3);
        h2pair(acc, v4, v5); h2pair(acc, v6, v7);
    }
    for (; e + 2 <= e1; e += 2) {
        uint2 v0 = X2[(size_t)g_esrc[e] * 32 + lane];
        uint2 v1 = X2[(size_t)g_esrc[e + 1] * 32 + lane];
        h2pair(acc, v0, v1);
    }
    if (e < e1) h2acc(acc, X2[(size_t)g_esrc[e] * 32 + lane]);

    __half2 o0 = __floats2half2_rn(acc.x, acc.y);
    __half2 o1 = __floats2half2_rn(acc.z, acc.w);
    uint2 st;
    st.x = *(unsigned*)&o0;
    st.y = *(unsigned*)&o1;
    ((uint2*)g_agg)[(size_t)gw * 32 + lane] = st;
}

// ---------------- persistent fused GIN MLP layer (fp16 mma m16n8k16) ----------------
// 512 threads, 16 warps, warp tile m32 x n32. Weights resident in smem (fp16).
__global__ __launch_bounds__(512, 1) void gin_layer(
    __half* __restrict__ Xout, int tap_off,
    const float* __restrict__ W1, const float* __restrict__ b1,
    const float* __restrict__ gam, const float* __restrict__ bet,
    const float* __restrict__ mu, const float* __restrict__ var,
    const float* __restrict__ W2, const float* __restrict__ b2)
{
    extern __shared__ __half smh[];
    __half* sW1 = smh;                      // 128 x AS2 fp16 (BN-folded W1)
    __half* sW2 = smh + 128 * AS2;          // 128 x AS2 fp16 W2
    __half* sA  = smh + 2 * 128 * AS2;      // 128 x AS2 fp16 tile (A, then H1)
    float* sB1    = (float*)(smh + 3 * 128 * AS2);
    float* sB2    = sB1 + 128;
    float* sTap   = sB2 + 128;
    float* sScale = sTap + 128;

    float* tap = g_tap + tap_off;

    const int tid = threadIdx.x;
    const int w = tid >> 5, lane = tid & 31;

    if (tid < 128) {
        float sc = gam[tid] * rsqrtf(var[tid] + 1e-5f);
        sScale[tid] = sc;
        sTap[tid] = 0.f;
        sB2[tid] = b2[tid];
        sB1[tid] = (b1[tid] - mu[tid]) * sc + bet[tid];
    }
    __syncthreads();   // sScale visible for weight fold

    // --- load both weight matrices once (float4 -> fp16) ---
    const float4* W14 = (const float4*)W1;
    const float4* W24 = (const float4*)W2;
    for (int idx = tid; idx < 4096; idx += 512) {
        int c = idx >> 5, k4 = (idx & 31) * 4;
        float s = sScale[c];
        float4 v1 = W14[idx];
        __half2 a0 = __floats2half2_rn(v1.x * s, v1.y * s);
        __half2 a1 = __floats2half2_rn(v1.z * s, v1.w * s);
        uint2 u1; u1.x = *(unsigned*)&a0; u1.y = *(unsigned*)&a1;
        *(uint2*)&sW1[c * AS2 + k4] = u1;
        float4 v2 = W24[idx];
        __half2 b0h = __floats2half2_rn(v2.x, v2.y);
        __half2 b1h = __floats2half2_rn(v2.z, v2.w);
        uint2 u2; u2.x = *(unsigned*)&b0h; u2.y = *(unsigned*)&b1h;
        *(uint2*)&sW2[c * AS2 + k4] = u2;
    }
    // (first in-loop __syncthreads covers weight visibility)

    // warp tiling: 16 warps = 4 row-tiles x 4 col-strips
    const int wr = w & 3, wc = w >> 2;
    const int rb = wr * 32, cb = wc * 32;
    const int gq = lane >> 2, q = lane & 3;

    float tS0[4], tS1[4];
#pragma unroll
    for (int nt = 0; nt < 4; nt++) { tS0[nt] = 0.f; tS1[nt] = 0.f; }

    const uint2* A2 = (const uint2*)g_agg;

    for (int tile = blockIdx.x; tile < NB; tile += gridDim.x) {
        const int rowBase = tile * 128;

        // --- A tile: straight fp16 copy from g_agg (no conversion) ---
        for (int idx = tid; idx < 4096; idx += 512) {
            int r = idx >> 5, c4 = idx & 31;
            int n = rowBase + r;
            uint2 v = make_uint2(0u, 0u);
            if (n < NN) v = A2[(size_t)n * 32 + c4];
            *(uint2*)&sA[r * AS2 + c4 * 4] = v;
        }
        __syncthreads();

        // --- GEMM1: H1 = ReLU(A @ W1'^T + b1') ---
        float acc1[2][4][4];
#pragma unroll
        for (int rt = 0; rt < 2; rt++)
#pragma unroll
            for (int nt = 0; nt < 4; nt++)
#pragma unroll
                for (int j = 0; j < 4; j++) acc1[rt][nt][j] = 0.f;

#pragma unroll
        for (int kt = 0; kt < 8; kt++) {
            int kh = kt * 16 + 2 * q;
            unsigned a00 = *(unsigned*)&sA[(rb + gq) * AS2 + kh];
            unsigned a01 = *(unsigned*)&sA[(rb + gq) * AS2 + kh + 8];
            unsigned a10 = *(unsigned*)&sA[(rb + 8 + gq) * AS2 + kh];
            unsigned a11 = *(unsigned*)&sA[(rb + 8 + gq) * AS2 + kh + 8];
            unsigned a20 = *(unsigned*)&sA[(rb + 16 + gq) * AS2 + kh];
            unsigned a21 = *(unsigned*)&sA[(rb + 16 + gq) * AS2 + kh + 8];
            unsigned a30 = *(unsigned*)&sA[(rb + 24 + gq) * AS2 + kh];
            unsigned a31 = *(unsigned*)&sA[(rb + 24 + gq) * AS2 + kh + 8];
#pragma unroll
            for (int nt = 0; nt < 4; nt++) {
                int n0 = cb + nt * 8 + gq;
                unsigned b0 = *(unsigned*)&sW1[n0 * AS2 + kh];
                unsigned b1v = *(unsigned*)&sW1[n0 * AS2 + kh + 8];
                mma16(acc1[0][nt], a00, a10, a01, a11, b0, b1v);
                mma16(acc1[1][nt], a20, a30, a21, a31, b0, b1v);
            }
        }
        __syncthreads();

        // --- H1 -> sA (fp16) ---
#pragma unroll
        for (int rt = 0; rt < 2; rt++) {
            int r0 = rb + 16 * rt + gq;
#pragma unroll
            for (int nt = 0; nt < 4; nt++) {
                int c0 = cb + nt * 8 + q * 2;
                float o00 = fmaxf(acc1[rt][nt][0] + sB1[c0], 0.f);
                float o01 = fmaxf(acc1[rt][nt][1] + sB1[c0 + 1], 0.f);
                float o10 = fmaxf(acc1[rt][nt][2] + sB1[c0], 0.f);
                float o11 = fmaxf(acc1[rt][nt][3] + sB1[c0 + 1], 0.f);
                __half2 h0 = __floats2half2_rn(o00, o01);
                __half2 h1 = __floats2half2_rn(o10, o11);
                *(unsigned*)&sA[r0 * AS2 + c0] = *(unsigned*)&h0;
                *(unsigned*)&sA[(r0 + 8) * AS2 + c0] = *(unsigned*)&h1;
            }
        }
        __syncthreads();

        // --- GEMM2: H2 = ReLU(H1 @ W2^T + b2) ---
        float acc2[2][4][4];
#pragma unroll
        for (int rt = 0; rt < 2; rt++)
#pragma unroll
            for (int nt = 0; nt < 4; nt++)
#pragma unroll
                for (int j = 0; j < 4; j++) acc2[rt][nt][j] = 0.f;

#pragma unroll
        for (int kt = 0; kt < 8; kt++) {
            int kh = kt * 16 + 2 * q;
            unsigned a00 = *(unsigned*)&sA[(rb + gq) * AS2 + kh];
            unsigned a01 = *(unsigned*)&sA[(rb + gq) * AS2 + kh + 8];
            unsigned a10 = *(unsigned*)&sA[(rb + 8 + gq) * AS2 + kh];
            unsigned a11 = *(unsigned*)&sA[(rb + 8 + gq) * AS2 + kh + 8];
            unsigned a20 = *(unsigned*)&sA[(rb + 16 + gq) * AS2 + kh];
            unsigned a21 = *(unsigned*)&sA[(rb + 16 + gq) * AS2 + kh + 8];
            unsigned a30 = *(unsigned*)&sA[(rb + 24 + gq) * AS2 + kh];
            unsigned a31 = *(unsigned*)&sA[(rb + 24 + gq) * AS2 + kh + 8];
#pragma unroll
            for (int nt = 0; nt < 4; nt++) {
                int n0 = cb + nt * 8 + gq;
                unsigned b0 = *(unsigned*)&sW2[n0 * AS2 + kh];
                unsigned b1v = *(unsigned*)&sW2[n0 * AS2 + kh + 8];
                mma16(acc2[0][nt], a00, a10, a01, a11, b0, b1v);
                mma16(acc2[1][nt], a20, a30, a21, a31, b0, b1v);
            }
        }

        // --- epilogue: write fp16 Xout, accumulate tap in fp32 regs ---
#pragma unroll
        for (int rt = 0; rt < 2; rt++) {
            int r0 = rowBase + rb + 16 * rt + gq;
            int r1 = r0 + 8;
            bool m0v = (r0 < NN), m1v = (r1 < NN);
#pragma unroll
            for (int nt = 0; nt < 4; nt++) {
                int c0 = cb + nt * 8 + q * 2;
                float o00 = m0v ? fmaxf(acc2[rt][nt][0] + sB2[c0], 0.f) : 0.f;
                float o01 = m0v ? fmaxf(acc2[rt][nt][1] + sB2[c0 + 1], 0.f) : 0.f;
                float o10 = m1v ? fmaxf(acc2[rt][nt][2] + sB2[c0], 0.f) : 0.f;
                float o11 = m1v ? fmaxf(acc2[rt][nt][3] + sB2[c0 + 1], 0.f) : 0.f;
                if (m0v) *(__half2*)&Xout[(size_t)r0 * 128 + c0] = __floats2half2_rn(o00, o01);
                if (m1v) *(__half2*)&Xout[(size_t)r1 * 128 + c0] = __floats2half2_rn(o10, o11);
                tS0[nt] += o00 + o10;
                tS1[nt] += o01 + o11;
            }
        }
        __syncthreads();   // sA reuse next tile
    }

    // --- final tap reduction ---
#pragma unroll
    for (int nt = 0; nt < 4; nt++) {
        float t0 = tS0[nt], t1 = tS1[nt];
#pragma unroll
        for (int o = 16; o >= 4; o >>= 1) {
            t0 += __shfl_xor_sync(0xffffffffu, t0, o);
            t1 += __shfl_xor_sync(0xffffffffu, t1, o);
        }
        if (gq == 0) {
            int c0 = cb + nt * 8 + q * 2;
            atomicAdd(&sTap[c0], t0);
            atomicAdd(&sTap[c0 + 1], t1);
        }
    }
    __syncthreads();
    if (tid < 128) atomicAdd(&tap[tid], sTap[tid]);
}

// ---------------- readout ----------------
__global__ void readout_k(const float* __restrict__ Wll, const float* __restrict__ bll,
                          float* __restrict__ out) {
    int w = threadIdx.x >> 5, lane = threadIdx.x & 31;
    if (w < 10) {
        float s = 0.f;
        for (int k = lane; k < 512; k += 32) s += g_tap[k] * Wll[w * 512 + k];
#pragma unroll
        for (int off = 16; off; off >>= 1) s += __shfl_xor_sync(0xffffffffu, s, off);
        if (lane == 0) out[w] = s + bll[w];
    }
}

// ---------------- host ----------------
extern "C" void kernel_launch(void* const* d_in, const int* in_sizes, int n_in,
                              void* d_out, int out_size) {
    const float* x   = (const float*)d_in[0];
    const int*   ei  = (const int*)d_in[1];
    const float* W1_0 = (const float*)d_in[2];
    const float* b1_0 = (const float*)d_in[3];
    const float* g0   = (const float*)d_in[4];
    const float* be0  = (const float*)d_in[5];
    const float* m0   = (const float*)d_in[6];
    const float* v0   = (const float*)d_in[7];
    const float* W2_0 = (const float*)d_in[8];
    const float* b2_0 = (const float*)d_in[9];
    const float* W1s  = (const float*)d_in[10];
    const float* b1s  = (const float*)d_in[11];
    const float* gs   = (const float*)d_in[12];
    const float* bes  = (const float*)d_in[13];
    const float* ms   = (const float*)d_in[14];
    const float* vs   = (const float*)d_in[15];
    const float* W2s  = (const float*)d_in[16];
    const float* b2s  = (const float*)d_in[17];
    const float* Wll  = (const float*)d_in[18];
    const float* bll  = (const float*)d_in[19];
    float* out = (float*)d_out;

    cudaFuncSetAttribute(gin_layer, cudaFuncAttributeMaxDynamicSharedMemorySize, SMEM_BYTES);

    const int* esrc_in = ei;        // edge_index[0] = src
    const int* edst_in = ei + NE;   // edge_index[1] = dst

    void* dDeg; cudaGetSymbolAddress(&dDeg, g_deg);
    cudaMemsetAsync(dDeg, 0, NN * sizeof(int), 0);

    hist_k<<<(NE + 255) / 256, 256>>>(edst_in);
    scan_lb_k<<<NSB, 256>>>();
    scatter_k<<<(NE + 255) / 256, 256>>>(esrc_in, edst_in, x);

    __half* dh0; cudaGetSymbolAddress((void**)&dh0, g_h0);
    __half* dh1; cudaGetSymbolAddress((void**)&dh1, g_h1);
    __half* dh2; cudaGetSymbolAddress((void**)&dh2, g_h2);

    const int aggGrid = (NN * 32 + 255) / 256;

    const __half* ins[4]  = {dh0, dh1, dh2, dh1};
    __half*       outs[4] = {dh1, dh2, dh1, dh2};

    agg_k<<<aggGrid, 256>>>(ins[0]);
    gin_layer<<<PGRID, 512, SMEM_BYTES>>>(outs[0], 0,
                                          W1_0, b1_0, g0, be0, m0, v0, W2_0, b2_0);
    for (int i = 1; i < 4; i++) {
        int off = i - 1;
        agg_k<<<aggGrid, 256>>>(ins[i]);
        gin_layer<<<PGRID, 512, SMEM_BYTES>>>(outs[i], i * 128,
                                              W1s + off * 16384, b1s + off * 128,
                                              gs + off * 128, bes + off * 128,
                                              ms + off * 128, vs + off * 128,
                                              W2s + off * 16384, b2s + off * 128);
    }
    readout_k<<<1, 320>>>(Wll, bll, out);
}